// round 13
// baseline (speedup 1.0000x reference)
#include <cuda_runtime.h>
#include <cuda_fp16.h>
#include <cstdint>
#include <math.h>

// ---------------------------------------------------------------------------
// Problem constants
// ---------------------------------------------------------------------------
#define L_SEQ 1024
#define B_SZ  16
#define D_SZ  1024
#define M_X   (L_SEQ * B_SZ)        // 16384 x-rows
#define N_W   3072                  // weight rows (gate-major permuted)
#define NPOS  16                    // physical k-positions (chunks of 64)
#define PLANE ((size_t)M_X * D_SZ)  // 16,777,216

#define NSEG 16
#define SEG_T (L_SEQ / NSEG)        // 64
#define NLANE (B_SZ * D_SZ)         // 16384

// ---------------------------------------------------------------------------
// Scratch (__device__ globals: allocation-free)
// ---------------------------------------------------------------------------
__device__ __align__(1024) __half g_xc[(size_t)M_X * 1024];   // 32 MiB
__device__ __align__(1024) __half g_wc[(size_t)N_W * 1024];   // 6 MiB
__device__ __half g_u0[PLANE];                                 // 33.5 MB
__device__ __half g_g1[PLANE];                                 // 33.5 MB
__device__ __half g_g2[PLANE];                                 // 33.5 MB
__device__ float g_segAx[NSEG * NLANE];
__device__ float g_segBx[NSEG * NLANE];
__device__ float g_cst  [NSEG * NLANE];

// ---------------------------------------------------------------------------
// helpers
// ---------------------------------------------------------------------------
__device__ __forceinline__ uint32_t smem_u32(const void* p) {
    return (uint32_t)__cvta_generic_to_shared(p);
}
__device__ __forceinline__ void cp_async16(uint32_t dst, const void* src) {
    asm volatile("cp.async.cg.shared.global [%0], [%1], 16;" :: "r"(dst), "l"(src));
}
__device__ __forceinline__ void cp_commit() {
    asm volatile("cp.async.commit_group;");
}
template <int N>
__device__ __forceinline__ void cp_wait() {
    asm volatile("cp.async.wait_group %0;" :: "n"(N));
}
__device__ __forceinline__ void ldsm_x4(uint32_t& r0, uint32_t& r1, uint32_t& r2,
                                        uint32_t& r3, uint32_t addr) {
    asm volatile("ldmatrix.sync.aligned.m8n8.x4.shared.b16 {%0,%1,%2,%3}, [%4];"
                 : "=r"(r0), "=r"(r1), "=r"(r2), "=r"(r3) : "r"(addr));
}
__device__ __forceinline__ void mma_fp16(float* d, const uint32_t* a, const uint32_t* b) {
    asm volatile(
        "mma.sync.aligned.m16n8k16.row.col.f32.f16.f16.f32 "
        "{%0,%1,%2,%3}, {%4,%5,%6,%7}, {%8,%9}, {%0,%1,%2,%3};"
        : "+f"(d[0]), "+f"(d[1]), "+f"(d[2]), "+f"(d[3])
        : "r"(a[0]), "r"(a[1]), "r"(a[2]), "r"(a[3]), "r"(b[0]), "r"(b[1]));
}
__device__ __forceinline__ uint32_t pack_h2(float a, float b) {
    __half2 h = __floats2half2_rn(a, b);
    return *reinterpret_cast<uint32_t*>(&h);
}
__device__ __forceinline__ float tanh_fast(float x) {
    float y;
    asm("tanh.approx.f32 %0, %1;" : "=f"(y) : "f"(x));
    return y;
}

// ---------------------------------------------------------------------------
// Fused conversion kernel (unchanged).
// ---------------------------------------------------------------------------
#define CONVX_BLOCKS 8192
#define CONVW_BLOCKS 6144

__global__ __launch_bounds__(256)
void conv_kernel(const float* __restrict__ X, const float* __restrict__ W) {
    if (blockIdx.x < CONVX_BLOCKS) {
        int gid = blockIdx.x * 256 + threadIdx.x;   // M_X * 128 threads
        int m  = gid >> 7;
        int k  = (gid & 127) * 8;

        const float4* xp = reinterpret_cast<const float4*>(X + (size_t)m * 1024 + k);
        float4 x0 = xp[0];
        float4 x1 = xp[1];

        uint4 hv;
        hv.x = pack_h2(x0.x, x0.y); hv.y = pack_h2(x0.z, x0.w);
        hv.z = pack_h2(x1.x, x1.y); hv.w = pack_h2(x1.z, x1.w);

        int chunk = k >> 6;
        uint32_t b = (uint32_t)(k & 63) * 2;
        uint32_t sw = b ^ (((uint32_t)m & 7u) << 4);
        char* base = (char*)g_xc;
        *reinterpret_cast<uint4*>(base + ((size_t)chunk * M_X + m) * 128 + sw) = hv;
    } else {
        int gid = (blockIdx.x - CONVX_BLOCKS) * 256 + threadIdx.x;  // N_W * 512
        int np = gid % N_W;
        int k  = (gid / N_W) * 2;

        int gate = np >> 10;
        int d    = np & 1023;
        int col  = 3 * d + gate;

        float w0 = W[(size_t)k * N_W + col];
        float w1 = W[(size_t)(k + 1) * N_W + col];

        int chunk = k >> 6;
        uint32_t b = (uint32_t)(k & 63) * 2;
        uint32_t sw = b ^ (((uint32_t)np & 7u) << 4);
        char* base = (char*)g_wc;
        *reinterpret_cast<uint32_t*>(base + ((size_t)chunk * N_W + np) * 128 + sw) =
            pack_h2(w0, w1);
    }
}

// ---------------------------------------------------------------------------
// mma.sync GEMM (unchanged from R11): 128x128x64 tile, 2 CTAs/SM, 3 stages.
// ---------------------------------------------------------------------------
#define W_OFF 0
#define X_OFF 16384
#define STAGE_BYTES 32768        // W 16KB + X 16KB
#define STAGES 3
#define SMEM_TOTAL (STAGES * STAGE_BYTES)   // 98304 (96 KB)
#define EPI_PITCH 132            // floats per staging row (128 + pad)

__global__ __launch_bounds__(256, 2)
void sru_gemm_mma(const float* __restrict__ bias) {
    extern __shared__ char smem[];
    const uint32_t sbase = smem_u32(smem);
    const int tid = threadIdx.x;
    const int wid = tid >> 5;
    const int l = tid & 31;

    const int bn = blockIdx.x;    // m tiles (128)
    const int bm = blockIdx.y;    // np tiles (24)

    const int npwarp = (wid & 1) * 64;
    const int mwarp  = (wid >> 1) * 32;

    const uint32_t swz = (uint32_t)(l & 7) << 4;
    const uint32_t aRow = npwarp + (l & 15);
    const uint32_t aHalf = (uint32_t)(l >> 4) << 4;     // 0 or 16
    const uint32_t bRow = mwarp + (l & 7) + ((l & 16) >> 1);
    const uint32_t bHalf = (uint32_t)(l & 8) << 1;      // 0 or 16

    const char* aSrcBase = (const char*)g_wc + (size_t)bm * 128 * 128;
    const char* bSrcBase = (const char*)g_xc + (size_t)bn * 128 * 128;

    float cacc[4][4][4];
    #pragma unroll
    for (int i = 0; i < 4; i++)
        #pragma unroll
        for (int j = 0; j < 4; j++)
            #pragma unroll
            for (int r = 0; r < 4; r++) cacc[i][j][r] = 0.0f;

    auto issue_pos = [&](int kc, int slot) {
        const uint32_t sb = sbase + slot * STAGE_BYTES;
        const char* wh = aSrcBase + (size_t)kc * N_W * 128;
        const char* xh = bSrcBase + (size_t)kc * M_X * 128;
        #pragma unroll
        for (int r = 0; r < 4; r++) {
            int off = (tid + r * 256) * 16;
            cp_async16(sb + W_OFF + off, wh + off);
        }
        #pragma unroll
        for (int r = 0; r < 4; r++) {
            int off = (tid + r * 256) * 16;
            cp_async16(sb + X_OFF + off, xh + off);
        }
        cp_commit();
    };

    issue_pos(0, 0);
    issue_pos(1, 1);

    for (int j = 0; j < NPOS; j++) {
        const int slot = j % 3;
        cp_wait<1>();
        __syncthreads();
        if (j + 2 < NPOS) issue_pos(j + 2, (j + 2) % 3);

        const uint32_t sb = sbase + slot * STAGE_BYTES;

        #pragma unroll
        for (int ks = 0; ks < 4; ks++) {
            const uint32_t kb = ks * 32;
            const uint32_t aCol = (kb + aHalf) ^ swz;
            const uint32_t bCol = (kb + bHalf) ^ swz;

            uint32_t bh[2][4];
            #pragma unroll
            for (int g = 0; g < 2; g++) {
                ldsm_x4(bh[g][0], bh[g][1], bh[g][2], bh[g][3],
                        sb + X_OFF + (bRow + g * 16) * 128 + bCol);
            }
            #pragma unroll
            for (int t = 0; t < 4; t++) {
                uint32_t a[4];
                ldsm_x4(a[0], a[1], a[2], a[3],
                        sb + W_OFF + (aRow + t * 16) * 128 + aCol);
                #pragma unroll
                for (int jj = 0; jj < 4; jj++)
                    mma_fp16(cacc[t][jj], a, &bh[jj >> 1][(jj & 1) * 2]);
            }
        }
    }

    // ---------------- epilogue ----------------
    __syncthreads();
    float* stag = (float*)smem;    // [128 m][EPI_PITCH np]

    #pragma unroll
    for (int i = 0; i < 4; i++) {
        const int np0 = npwarp + i * 16 + (l >> 2);
        #pragma unroll
        for (int jj = 0; jj < 4; jj++) {
            const int m0 = mwarp + jj * 8 + (l & 3) * 2;
            stag[(size_t)m0 * EPI_PITCH + np0]           = cacc[i][jj][0];
            stag[(size_t)(m0 + 1) * EPI_PITCH + np0]     = cacc[i][jj][1];
            stag[(size_t)m0 * EPI_PITCH + np0 + 8]       = cacc[i][jj][2];
            stag[(size_t)(m0 + 1) * EPI_PITCH + np0 + 8] = cacc[i][jj][3];
        }
    }
    __syncthreads();

    const int gate = bm >> 3;
    const int d0 = (bm & 7) * 128;
    __half* plane = (gate == 0) ? g_u0 : ((gate == 1) ? g_g1 : g_g2);

    for (int idx = tid; idx < 128 * 64; idx += 256) {
        const int m = idx >> 6;
        const int np2 = (idx & 63) * 2;
        float v0 = stag[(size_t)m * EPI_PITCH + np2];
        float v1 = stag[(size_t)m * EPI_PITCH + np2 + 1];
        if (gate) {
            const float b0 = bias[(gate - 1) * D_SZ + d0 + np2];
            const float b1 = bias[(gate - 1) * D_SZ + d0 + np2 + 1];
            v0 = 1.0f / (1.0f + __expf(-(v0 + b0)));
            v1 = 1.0f / (1.0f + __expf(-(v1 + b1)));
        }
        __half2 hv = __floats2half2_rn(v0, v1);
        *reinterpret_cast<__half2*>(
            &plane[(size_t)(bn * 128 + m) * D_SZ + d0 + np2]) = hv;
    }
}

// ---------------------------------------------------------------------------
// Segmented scan (4 lanes per thread).  c_t = g1*c + u0*(1-g1)
// ---------------------------------------------------------------------------
__global__ __launch_bounds__(256)
void scan_seg_kernel() {
    const int gid = blockIdx.x * blockDim.x + threadIdx.x;  // NSEG * 4096
    const int lane4 = (gid & 4095) * 4;
    const int s = gid >> 12;
    size_t o = ((size_t)s * SEG_T * NLANE + lane4) >> 2;    // uint2 index (4 halves)
    const uint2* __restrict__ u0 = (const uint2*)g_u0;
    const uint2* __restrict__ g1 = (const uint2*)g_g1;
    float A[4] = {1.0f, 1.0f, 1.0f, 1.0f};
    float Bv[4] = {0.0f, 0.0f, 0.0f, 0.0f};
    #pragma unroll 8
    for (int t = 0; t < SEG_T; t++) {
        const uint2 ar = g1[o];
        const uint2 ur = u0[o];
        const float2 a0 = __half22float2(*reinterpret_cast<const __half2*>(&ar.x));
        const float2 a1 = __half22float2(*reinterpret_cast<const __half2*>(&ar.y));
        const float2 u0v = __half22float2(*reinterpret_cast<const __half2*>(&ur.x));
        const float2 u1v = __half22float2(*reinterpret_cast<const __half2*>(&ur.y));
        const float a[4] = {a0.x, a0.y, a1.x, a1.y};
        const float u[4] = {u0v.x, u0v.y, u1v.x, u1v.y};
        #pragma unroll
        for (int q = 0; q < 4; q++) {
            Bv[q] = Bv[q] * a[q] + u[q] * (1.0f - a[q]);
            A[q] *= a[q];
        }
        o += NLANE / 4;
    }
    *reinterpret_cast<float4*>(&g_segAx[s * NLANE + lane4]) =
        make_float4(A[0], A[1], A[2], A[3]);
    *reinterpret_cast<float4*>(&g_segBx[s * NLANE + lane4]) =
        make_float4(Bv[0], Bv[1], Bv[2], Bv[3]);
}

// Prefix across segments: prefetch all coefficients (MLP=2*NSEG), 2 lanes/thread.
__global__ __launch_bounds__(256)
void scan_prefix_kernel(const float* __restrict__ c0) {
    const int lane2 = (blockIdx.x * blockDim.x + threadIdx.x) * 2;  // 8192 threads
    float2 A[NSEG], Bv[NSEG];
    #pragma unroll
    for (int s = 0; s < NSEG; s++)
        A[s] = *reinterpret_cast<const float2*>(&g_segAx[s * NLANE + lane2]);
    #pragma unroll
    for (int s = 0; s < NSEG; s++)
        Bv[s] = *reinterpret_cast<const float2*>(&g_segBx[s * NLANE + lane2]);
    float2 c = *reinterpret_cast<const float2*>(&c0[lane2]);
    #pragma unroll
    for (int s = 0; s < NSEG; s++) {
        *reinterpret_cast<float2*>(&g_cst[s * NLANE + lane2]) = c;
        c.x = A[s].x * c.x + Bv[s].x;
        c.y = A[s].y * c.y + Bv[s].y;
    }
}

// ---------------------------------------------------------------------------
// Output pass (4 lanes per thread, HW tanh).
// ---------------------------------------------------------------------------
__global__ __launch_bounds__(256)
void scan_out_kernel(float* __restrict__ out) {
    const int gid = blockIdx.x * blockDim.x + threadIdx.x;  // NSEG * 4096
    const int lane4 = (gid & 4095) * 4;
    const int s = gid >> 12;
    const uint2* __restrict__ u0 = (const uint2*)g_u0;
    const uint2* __restrict__ g1 = (const uint2*)g_g1;
    const uint2* __restrict__ g2 = (const uint2*)g_g2;
    float4 c4 = *reinterpret_cast<const float4*>(&g_cst[s * NLANE + lane4]);
    float c[4] = {c4.x, c4.y, c4.z, c4.w};
    size_t e = (size_t)s * SEG_T * NLANE + lane4;           // element index
    size_t o = e >> 2;                                      // uint2 index

    // x read from the packed swizzled fp16 operand g_xc: d fixed, m += 16/t.
    const int m0 = (int)(e >> 10);
    const int d  = lane4 & 1023;
    const char* xbase = (const char*)g_xc
        + ((size_t)(d >> 6) * M_X + m0) * 128
        + (((uint32_t)(d & 63) * 2) ^ (((uint32_t)m0 & 7u) << 4));

    #pragma unroll 4
    for (int t = 0; t < SEG_T; t++) {
        const uint2 ur = u0[o];
        const uint2 ar = g1[o];
        const uint2 br = g2[o];
        const uint2 xr = *reinterpret_cast<const uint2*>(xbase + (size_t)t * 2048);
        const float2 u01 = __half22float2(*reinterpret_cast<const __half2*>(&ur.x));
        const float2 u23 = __half22float2(*reinterpret_cast<const __half2*>(&ur.y));
        const float2 a01 = __half22float2(*reinterpret_cast<const __half2*>(&ar.x));
        const float2 a23 = __half22float2(*reinterpret_cast<const __half2*>(&ar.y));
        const float2 b01 = __half22float2(*reinterpret_cast<const __half2*>(&br.x));
        const float2 b23 = __half22float2(*reinterpret_cast<const __half2*>(&br.y));
        const float2 x01 = __half22float2(*reinterpret_cast<const __half2*>(&xr.x));
        const float2 x23 = __half22float2(*reinterpret_cast<const __half2*>(&xr.y));
        const float u[4] = {u01.x, u01.y, u23.x, u23.y};
        const float a[4] = {a01.x, a01.y, a23.x, a23.y};
        const float b[4] = {b01.x, b01.y, b23.x, b23.y};
        const float xv[4] = {x01.x, x01.y, x23.x, x23.y};
        float4 h;
        float* hp = &h.x;
        #pragma unroll
        for (int q = 0; q < 4; q++) {
            c[q] = (c[q] - u[q]) * a[q] + u[q];
            hp[q] = (tanh_fast(c[q]) - xv[q]) * b[q] + xv[q];
        }
        *reinterpret_cast<float4*>(&out[e]) = h;
        e += NLANE;
        o += NLANE / 4;
    }
    if (s == NSEG - 1)
        *reinterpret_cast<float4*>(&out[PLANE + lane4]) =
            make_float4(c[0], c[1], c[2], c[3]);   // c_last
}

// ---------------------------------------------------------------------------
// Launch
// ---------------------------------------------------------------------------
extern "C" void kernel_launch(void* const* d_in, const int* in_sizes, int n_in,
                              void* d_out, int out_size) {
    const float* x      = (const float*)d_in[0];  // (L,B,D)
    const float* weight = (const float*)d_in[1];  // (D, 3D)
    const float* bias   = (const float*)d_in[2];  // (2D)
    const float* c0     = (const float*)d_in[3];  // (B,D)
    float* out = (float*)d_out;                   // h then c_last

    conv_kernel<<<CONVX_BLOCKS + CONVW_BLOCKS, 256>>>(x, weight);

    static int smem_set = 0;
    if (!smem_set) {
        cudaFuncSetAttribute(sru_gemm_mma, cudaFuncAttributeMaxDynamicSharedMemorySize,
                             SMEM_TOTAL);
        smem_set = 1;
    }
    sru_gemm_mma<<<dim3(M_X / 128, N_W / 128), 256, SMEM_TOTAL>>>(bias);

    scan_seg_kernel<<<(NSEG * 4096) / 256, 256>>>();
    scan_prefix_kernel<<<8192 / 256, 256>>>(c0);
    scan_out_kernel<<<(NSEG * 4096) / 256, 256>>>(out);
}

// round 14
// speedup vs baseline: 1.0340x; 1.0340x over previous
#include <cuda_runtime.h>
#include <cuda_fp16.h>
#include <cstdint>
#include <math.h>

// ---------------------------------------------------------------------------
// Problem constants
// ---------------------------------------------------------------------------
#define L_SEQ 1024
#define B_SZ  16
#define D_SZ  1024
#define M_X   (L_SEQ * B_SZ)        // 16384 x-rows
#define N_W   3072                  // weight rows (gate-major permuted)
#define NPOS  16                    // physical k-positions (chunks of 64)
#define PLANE ((size_t)M_X * D_SZ)  // 16,777,216

#define NSEG 16
#define SEG_T (L_SEQ / NSEG)        // 64
#define NLANE (B_SZ * D_SZ)         // 16384

// ---------------------------------------------------------------------------
// Scratch (__device__ globals: allocation-free)
// ---------------------------------------------------------------------------
__device__ __align__(1024) __half g_xc[(size_t)M_X * 1024];   // 32 MiB
__device__ __align__(1024) __half g_wc[(size_t)N_W * 1024];   // 6 MiB
__device__ __half g_u0[PLANE];                                 // 33.5 MB
__device__ __half g_g1[PLANE];                                 // 33.5 MB
__device__ __half g_g2[PLANE];                                 // 33.5 MB
__device__ float g_segAx[NSEG * NLANE];
__device__ float g_segBx[NSEG * NLANE];
__device__ float g_cst  [NSEG * NLANE];

// ---------------------------------------------------------------------------
// helpers
// ---------------------------------------------------------------------------
__device__ __forceinline__ uint32_t smem_u32(const void* p) {
    return (uint32_t)__cvta_generic_to_shared(p);
}
__device__ __forceinline__ void cp_async16(uint32_t dst, const void* src) {
    asm volatile("cp.async.cg.shared.global [%0], [%1], 16;" :: "r"(dst), "l"(src));
}
__device__ __forceinline__ void cp_commit() {
    asm volatile("cp.async.commit_group;");
}
template <int N>
__device__ __forceinline__ void cp_wait() {
    asm volatile("cp.async.wait_group %0;" :: "n"(N));
}
__device__ __forceinline__ void ldsm_x4(uint32_t& r0, uint32_t& r1, uint32_t& r2,
                                        uint32_t& r3, uint32_t addr) {
    asm volatile("ldmatrix.sync.aligned.m8n8.x4.shared.b16 {%0,%1,%2,%3}, [%4];"
                 : "=r"(r0), "=r"(r1), "=r"(r2), "=r"(r3) : "r"(addr));
}
__device__ __forceinline__ void mma_fp16(float* d, const uint32_t* a, const uint32_t* b) {
    asm volatile(
        "mma.sync.aligned.m16n8k16.row.col.f32.f16.f16.f32 "
        "{%0,%1,%2,%3}, {%4,%5,%6,%7}, {%8,%9}, {%0,%1,%2,%3};"
        : "+f"(d[0]), "+f"(d[1]), "+f"(d[2]), "+f"(d[3])
        : "r"(a[0]), "r"(a[1]), "r"(a[2]), "r"(a[3]), "r"(b[0]), "r"(b[1]));
}
__device__ __forceinline__ uint32_t pack_h2(float a, float b) {
    __half2 h = __floats2half2_rn(a, b);
    return *reinterpret_cast<uint32_t*>(&h);
}
__device__ __forceinline__ float tanh_fast(float x) {
    float y;
    asm("tanh.approx.f32 %0, %1;" : "=f"(y) : "f"(x));
    return y;
}

// ---------------------------------------------------------------------------
// Fused conversion kernel.
// Blocks [0, 8192): conv_x — X[m][k] fp32 -> packed swizzled fp16 tiles
// Blocks [8192, 14336): conv_w — W[k][3d+gate] -> rows n' = gate*1024+d
// ---------------------------------------------------------------------------
#define CONVX_BLOCKS 8192
#define CONVW_BLOCKS 6144

__global__ __launch_bounds__(256)
void conv_kernel(const float* __restrict__ X, const float* __restrict__ W) {
    if (blockIdx.x < CONVX_BLOCKS) {
        int gid = blockIdx.x * 256 + threadIdx.x;   // M_X * 128 threads
        int m  = gid >> 7;
        int k  = (gid & 127) * 8;

        const float4* xp = reinterpret_cast<const float4*>(X + (size_t)m * 1024 + k);
        float4 x0 = xp[0];
        float4 x1 = xp[1];

        uint4 hv;
        hv.x = pack_h2(x0.x, x0.y); hv.y = pack_h2(x0.z, x0.w);
        hv.z = pack_h2(x1.x, x1.y); hv.w = pack_h2(x1.z, x1.w);

        int chunk = k >> 6;
        uint32_t b = (uint32_t)(k & 63) * 2;
        uint32_t sw = b ^ (((uint32_t)m & 7u) << 4);
        char* base = (char*)g_xc;
        *reinterpret_cast<uint4*>(base + ((size_t)chunk * M_X + m) * 128 + sw) = hv;
    } else {
        int gid = (blockIdx.x - CONVX_BLOCKS) * 256 + threadIdx.x;  // N_W * 512
        int np = gid % N_W;
        int k  = (gid / N_W) * 2;

        int gate = np >> 10;
        int d    = np & 1023;
        int col  = 3 * d + gate;

        float w0 = W[(size_t)k * N_W + col];
        float w1 = W[(size_t)(k + 1) * N_W + col];

        int chunk = k >> 6;
        uint32_t b = (uint32_t)(k & 63) * 2;
        uint32_t sw = b ^ (((uint32_t)np & 7u) << 4);
        char* base = (char*)g_wc;
        *reinterpret_cast<uint32_t*>(base + ((size_t)chunk * N_W + np) * 128 + sw) =
            pack_h2(w0, w1);
    }
}

// ---------------------------------------------------------------------------
// mma.sync GEMM: C[np][m] = sum_k W[np][k] * X[m][k]  (fp16 single pass)
// CTA tile 128(np) x 128(m) x 64(k); 256 threads = 8 warps (2 np x 4 m).
// 3-stage x 32KB cp.async pipeline; 96KB smem => 2 CTAs/SM.
// ---------------------------------------------------------------------------
#define W_OFF 0
#define X_OFF 16384
#define STAGE_BYTES 32768        // W 16KB + X 16KB
#define STAGES 3
#define SMEM_TOTAL (STAGES * STAGE_BYTES)   // 98304 (96 KB)
#define EPI_PITCH 132            // floats per staging row (128 + pad)

__global__ __launch_bounds__(256, 2)
void sru_gemm_mma(const float* __restrict__ bias) {
    extern __shared__ char smem[];
    const uint32_t sbase = smem_u32(smem);
    const int tid = threadIdx.x;
    const int wid = tid >> 5;
    const int l = tid & 31;

    const int bn = blockIdx.x;    // m tiles (128)
    const int bm = blockIdx.y;    // np tiles (24)

    const int npwarp = (wid & 1) * 64;
    const int mwarp  = (wid >> 1) * 32;

    // ldmatrix per-lane addressing constants
    const uint32_t swz = (uint32_t)(l & 7) << 4;
    const uint32_t aRow = npwarp + (l & 15);
    const uint32_t aHalf = (uint32_t)(l >> 4) << 4;     // 0 or 16
    const uint32_t bRow = mwarp + (l & 7) + ((l & 16) >> 1);
    const uint32_t bHalf = (uint32_t)(l & 8) << 1;      // 0 or 16

    // cp.async sources for this CTA
    const char* aSrcBase = (const char*)g_wc + (size_t)bm * 128 * 128;
    const char* bSrcBase = (const char*)g_xc + (size_t)bn * 128 * 128;

    float cacc[4][4][4];
    #pragma unroll
    for (int i = 0; i < 4; i++)
        #pragma unroll
        for (int j = 0; j < 4; j++)
            #pragma unroll
            for (int r = 0; r < 4; r++) cacc[i][j][r] = 0.0f;

    // Load one k-position: W (16KB) + X (16KB)
    auto issue_pos = [&](int kc, int slot) {
        const uint32_t sb = sbase + slot * STAGE_BYTES;
        const char* wh = aSrcBase + (size_t)kc * N_W * 128;
        const char* xh = bSrcBase + (size_t)kc * M_X * 128;
        #pragma unroll
        for (int r = 0; r < 4; r++) {
            int off = (tid + r * 256) * 16;
            cp_async16(sb + W_OFF + off, wh + off);
        }
        #pragma unroll
        for (int r = 0; r < 4; r++) {
            int off = (tid + r * 256) * 16;
            cp_async16(sb + X_OFF + off, xh + off);
        }
        cp_commit();
    };

    issue_pos(0, 0);
    issue_pos(1, 1);

    for (int j = 0; j < NPOS; j++) {
        const int slot = j % 3;
        cp_wait<1>();
        __syncthreads();
        // Slot (j+2)%3 == (j-1)%3 was last read during compute of j-1; the
        // barrier above proves every warp finished that compute.
        if (j + 2 < NPOS) issue_pos(j + 2, (j + 2) % 3);

        const uint32_t sb = sbase + slot * STAGE_BYTES;

        #pragma unroll
        for (int ks = 0; ks < 4; ks++) {
            const uint32_t kb = ks * 32;
            const uint32_t aCol = (kb + aHalf) ^ swz;
            const uint32_t bCol = (kb + bHalf) ^ swz;

            uint32_t bh[2][4];
            #pragma unroll
            for (int g = 0; g < 2; g++) {
                ldsm_x4(bh[g][0], bh[g][1], bh[g][2], bh[g][3],
                        sb + X_OFF + (bRow + g * 16) * 128 + bCol);
            }
            #pragma unroll
            for (int t = 0; t < 4; t++) {
                uint32_t a[4];
                ldsm_x4(a[0], a[1], a[2], a[3],
                        sb + W_OFF + (aRow + t * 16) * 128 + aCol);
                #pragma unroll
                for (int jj = 0; jj < 4; jj++)
                    mma_fp16(cacc[t][jj], a, &bh[jj >> 1][(jj & 1) * 2]);
            }
        }
    }

    // ---------------- epilogue ----------------
    __syncthreads();   // done reading pipeline smem
    float* stag = (float*)smem;    // [128 m][EPI_PITCH np]  (67.6 KB < 96 KB)

    #pragma unroll
    for (int i = 0; i < 4; i++) {
        const int np0 = npwarp + i * 16 + (l >> 2);
        #pragma unroll
        for (int jj = 0; jj < 4; jj++) {
            const int m0 = mwarp + jj * 8 + (l & 3) * 2;
            stag[(size_t)m0 * EPI_PITCH + np0]           = cacc[i][jj][0];
            stag[(size_t)(m0 + 1) * EPI_PITCH + np0]     = cacc[i][jj][1];
            stag[(size_t)m0 * EPI_PITCH + np0 + 8]       = cacc[i][jj][2];
            stag[(size_t)(m0 + 1) * EPI_PITCH + np0 + 8] = cacc[i][jj][3];
        }
    }
    __syncthreads();

    // This CTA covers a single gate: np range [bm*128, bm*128+128)
    const int gate = bm >> 3;
    const int d0 = (bm & 7) * 128;
    __half* plane = (gate == 0) ? g_u0 : ((gate == 1) ? g_g1 : g_g2);

    // 128 m x 64 half2 stores
    for (int idx = tid; idx < 128 * 64; idx += 256) {
        const int m = idx >> 6;
        const int np2 = (idx & 63) * 2;
        float v0 = stag[(size_t)m * EPI_PITCH + np2];
        float v1 = stag[(size_t)m * EPI_PITCH + np2 + 1];
        if (gate) {
            const float b0 = bias[(gate - 1) * D_SZ + d0 + np2];
            const float b1 = bias[(gate - 1) * D_SZ + d0 + np2 + 1];
            v0 = 1.0f / (1.0f + __expf(-(v0 + b0)));
            v1 = 1.0f / (1.0f + __expf(-(v1 + b1)));
        }
        __half2 hv = __floats2half2_rn(v0, v1);
        *reinterpret_cast<__half2*>(
            &plane[(size_t)(bn * 128 + m) * D_SZ + d0 + np2]) = hv;
    }
}

// ---------------------------------------------------------------------------
// Segmented scan (vectorized: 2 lanes per thread).
// c_t = g1*c + u0*(1-g1)  (affine in c)
// ---------------------------------------------------------------------------
__global__ __launch_bounds__(256)
void scan_seg_kernel() {
    const int gid = blockIdx.x * blockDim.x + threadIdx.x;  // NSEG * 8192
    const int lane2 = (gid & 8191) * 2;
    const int s = gid >> 13;
    size_t o = ((size_t)s * SEG_T * NLANE + lane2) >> 1;    // half2 index
    const __half2* __restrict__ u0 = (const __half2*)g_u0;
    const __half2* __restrict__ g1 = (const __half2*)g_g1;
    float A0 = 1.0f, B0 = 0.0f, A1 = 1.0f, B1 = 0.0f;
    #pragma unroll 8
    for (int t = 0; t < SEG_T; t++) {
        const float2 a = __half22float2(g1[o]);
        const float2 u = __half22float2(u0[o]);
        B0 = B0 * a.x + u.x * (1.0f - a.x);
        B1 = B1 * a.y + u.y * (1.0f - a.y);
        A0 *= a.x;
        A1 *= a.y;
        o += NLANE / 2;
    }
    *reinterpret_cast<float2*>(&g_segAx[s * NLANE + lane2]) = make_float2(A0, A1);
    *reinterpret_cast<float2*>(&g_segBx[s * NLANE + lane2]) = make_float2(B0, B1);
}

// Prefix across segments: prefetch ALL segment coefficients first (MLP=32),
// then run the short dependent chain. One lane per thread.
__global__ __launch_bounds__(256)
void scan_prefix_kernel(const float* __restrict__ c0) {
    const int lane = blockIdx.x * blockDim.x + threadIdx.x;  // 16384 threads
    float A[NSEG], Bv[NSEG];
    #pragma unroll
    for (int s = 0; s < NSEG; s++) A[s] = g_segAx[s * NLANE + lane];
    #pragma unroll
    for (int s = 0; s < NSEG; s++) Bv[s] = g_segBx[s * NLANE + lane];
    float c = c0[lane];
    #pragma unroll
    for (int s = 0; s < NSEG; s++) {
        g_cst[s * NLANE + lane] = c;
        c = A[s] * c + Bv[s];
    }
}

__global__ __launch_bounds__(256)
void scan_out_kernel(float* __restrict__ out) {
    const int gid = blockIdx.x * blockDim.x + threadIdx.x;  // NSEG * 8192
    const int lane2 = (gid & 8191) * 2;
    const int s = gid >> 13;
    const __half2* __restrict__ u0 = (const __half2*)g_u0;
    const __half2* __restrict__ g1 = (const __half2*)g_g1;
    const __half2* __restrict__ g2 = (const __half2*)g_g2;
    float2 c = *reinterpret_cast<const float2*>(&g_cst[s * NLANE + lane2]);
    size_t e = (size_t)s * SEG_T * NLANE + lane2;           // element index
    size_t o = e >> 1;                                      // half2 index

    // x read from the packed swizzled fp16 operand g_xc.
    // element (m, d): chunk = d>>6, byte = (chunk*M_X + m)*128
    //                 + ((d&63)*2 ^ ((m&7)<<4));  here d fixed, m += 16 per t.
    const int m0 = (int)(e >> 10);          // initial row
    const int d  = lane2 & 1023;
    const char* xbase = (const char*)g_xc
        + ((size_t)(d >> 6) * M_X + m0) * 128
        + (((uint32_t)(d & 63) * 2) ^ (((uint32_t)m0 & 7u) << 4));

    #pragma unroll 4
    for (int t = 0; t < SEG_T; t++) {
        const float2 u = __half22float2(u0[o]);
        const float2 a = __half22float2(g1[o]);
        const float2 b = __half22float2(g2[o]);
        const float2 xv = __half22float2(
            *reinterpret_cast<const __half2*>(xbase + (size_t)t * 2048));
        c.x = (c.x - u.x) * a.x + u.x;
        c.y = (c.y - u.y) * a.y + u.y;
        float2 h;
        h.x = (tanh_fast(c.x) - xv.x) * b.x + xv.x;
        h.y = (tanh_fast(c.y) - xv.y) * b.y + xv.y;
        *reinterpret_cast<float2*>(&out[e]) = h;
        e += NLANE;
        o += NLANE / 2;
    }
    if (s == NSEG - 1)
        *reinterpret_cast<float2*>(&out[PLANE + lane2]) = c;   // c_last
}

// ---------------------------------------------------------------------------
// Launch
// ---------------------------------------------------------------------------
extern "C" void kernel_launch(void* const* d_in, const int* in_sizes, int n_in,
                              void* d_out, int out_size) {
    const float* x      = (const float*)d_in[0];  // (L,B,D)
    const float* weight = (const float*)d_in[1];  // (D, 3D)
    const float* bias   = (const float*)d_in[2];  // (2D)
    const float* c0     = (const float*)d_in[3];  // (B,D)
    float* out = (float*)d_out;                   // h then c_last

    conv_kernel<<<CONVX_BLOCKS + CONVW_BLOCKS, 256>>>(x, weight);

    static int smem_set = 0;
    if (!smem_set) {
        cudaFuncSetAttribute(sru_gemm_mma, cudaFuncAttributeMaxDynamicSharedMemorySize,
                             SMEM_TOTAL);
        smem_set = 1;
    }
    sru_gemm_mma<<<dim3(M_X / 128, N_W / 128), 256, SMEM_TOTAL>>>(bias);

    scan_seg_kernel<<<(NSEG * 8192) / 256, 256>>>();
    scan_prefix_kernel<<<NLANE / 256, 256>>>(c0);
    scan_out_kernel<<<(NSEG * 8192) / 256, 256>>>(out);
}

// round 15
// speedup vs baseline: 1.0529x; 1.0183x over previous
#include <cuda_runtime.h>
#include <cuda_fp16.h>
#include <cstdint>
#include <math.h>

// ---------------------------------------------------------------------------
// Problem constants
// ---------------------------------------------------------------------------
#define L_SEQ 1024
#define B_SZ  16
#define D_SZ  1024
#define M_X   (L_SEQ * B_SZ)        // 16384 x-rows
#define N_W   3072                  // weight rows (gate-major permuted)
#define NPOS  16                    // physical k-positions (chunks of 64)
#define PLANE ((size_t)M_X * D_SZ)  // 16,777,216

#define NSEG 16
#define SEG_T (L_SEQ / NSEG)        // 64
#define NLANE (B_SZ * D_SZ)         // 16384

// ---------------------------------------------------------------------------
// Scratch (__device__ globals: allocation-free)
// ---------------------------------------------------------------------------
__device__ __align__(1024) __half g_xc[(size_t)M_X * 1024];   // 32 MiB
__device__ __align__(1024) __half g_wc[(size_t)N_W * 1024];   // 6 MiB
__device__ __half g_u0[PLANE];                                 // 33.5 MB
__device__ __half g_g1[PLANE];                                 // 33.5 MB
__device__ __half g_g2[PLANE];                                 // 33.5 MB
__device__ float g_segAx[NSEG * NLANE];
__device__ float g_segBx[NSEG * NLANE];
__device__ float g_cst  [NSEG * NLANE];

// ---------------------------------------------------------------------------
// helpers
// ---------------------------------------------------------------------------
__device__ __forceinline__ uint32_t smem_u32(const void* p) {
    return (uint32_t)__cvta_generic_to_shared(p);
}
__device__ __forceinline__ void cp_async16(uint32_t dst, const void* src) {
    asm volatile("cp.async.cg.shared.global [%0], [%1], 16;" :: "r"(dst), "l"(src));
}
__device__ __forceinline__ void cp_commit() {
    asm volatile("cp.async.commit_group;");
}
template <int N>
__device__ __forceinline__ void cp_wait() {
    asm volatile("cp.async.wait_group %0;" :: "n"(N));
}
__device__ __forceinline__ void ldsm_x4(uint32_t& r0, uint32_t& r1, uint32_t& r2,
                                        uint32_t& r3, uint32_t addr) {
    asm volatile("ldmatrix.sync.aligned.m8n8.x4.shared.b16 {%0,%1,%2,%3}, [%4];"
                 : "=r"(r0), "=r"(r1), "=r"(r2), "=r"(r3) : "r"(addr));
}
__device__ __forceinline__ void mma_fp16(float* d, const uint32_t* a, const uint32_t* b) {
    asm volatile(
        "mma.sync.aligned.m16n8k16.row.col.f32.f16.f16.f32 "
        "{%0,%1,%2,%3}, {%4,%5,%6,%7}, {%8,%9}, {%0,%1,%2,%3};"
        : "+f"(d[0]), "+f"(d[1]), "+f"(d[2]), "+f"(d[3])
        : "r"(a[0]), "r"(a[1]), "r"(a[2]), "r"(a[3]), "r"(b[0]), "r"(b[1]));
}
__device__ __forceinline__ uint32_t pack_h2(float a, float b) {
    __half2 h = __floats2half2_rn(a, b);
    return *reinterpret_cast<uint32_t*>(&h);
}
__device__ __forceinline__ float tanh_fast(float x) {
    float y;
    asm("tanh.approx.f32 %0, %1;" : "=f"(y) : "f"(x));
    return y;
}

// ---------------------------------------------------------------------------
// Fused conversion kernel.
// ---------------------------------------------------------------------------
#define CONVX_BLOCKS 8192
#define CONVW_BLOCKS 6144

__global__ __launch_bounds__(256)
void conv_kernel(const float* __restrict__ X, const float* __restrict__ W) {
    if (blockIdx.x < CONVX_BLOCKS) {
        int gid = blockIdx.x * 256 + threadIdx.x;   // M_X * 128 threads
        int m  = gid >> 7;
        int k  = (gid & 127) * 8;

        const float4* xp = reinterpret_cast<const float4*>(X + (size_t)m * 1024 + k);
        float4 x0 = xp[0];
        float4 x1 = xp[1];

        uint4 hv;
        hv.x = pack_h2(x0.x, x0.y); hv.y = pack_h2(x0.z, x0.w);
        hv.z = pack_h2(x1.x, x1.y); hv.w = pack_h2(x1.z, x1.w);

        int chunk = k >> 6;
        uint32_t b = (uint32_t)(k & 63) * 2;
        uint32_t sw = b ^ (((uint32_t)m & 7u) << 4);
        char* base = (char*)g_xc;
        *reinterpret_cast<uint4*>(base + ((size_t)chunk * M_X + m) * 128 + sw) = hv;
    } else {
        int gid = (blockIdx.x - CONVX_BLOCKS) * 256 + threadIdx.x;  // N_W * 512
        int np = gid % N_W;
        int k  = (gid / N_W) * 2;

        int gate = np >> 10;
        int d    = np & 1023;
        int col  = 3 * d + gate;

        float w0 = W[(size_t)k * N_W + col];
        float w1 = W[(size_t)(k + 1) * N_W + col];

        int chunk = k >> 6;
        uint32_t b = (uint32_t)(k & 63) * 2;
        uint32_t sw = b ^ (((uint32_t)np & 7u) << 4);
        char* base = (char*)g_wc;
        *reinterpret_cast<uint32_t*>(base + ((size_t)chunk * N_W + np) * 128 + sw) =
            pack_h2(w0, w1);
    }
}

// ---------------------------------------------------------------------------
// mma.sync GEMM: C[np][m] = sum_k W[np][k] * X[m][k]  (fp16 single pass)
// CTA tile 128(np) x 128(m) x 64(k); 256 threads = 8 warps (2 np x 4 m).
// 3-stage x 32KB cp.async pipeline; 96KB smem => 2 CTAs/SM.
// bm_off splits the grid: gates 0,1 (bm 0..15) vs gate 2 (bm 16..23).
// ---------------------------------------------------------------------------
#define W_OFF 0
#define X_OFF 16384
#define STAGE_BYTES 32768        // W 16KB + X 16KB
#define STAGES 3
#define SMEM_TOTAL (STAGES * STAGE_BYTES)   // 98304 (96 KB)
#define EPI_PITCH 132            // floats per staging row (128 + pad)

__global__ __launch_bounds__(256, 2)
void sru_gemm_mma(const float* __restrict__ bias, int bm_off) {
    extern __shared__ char smem[];
    const uint32_t sbase = smem_u32(smem);
    const int tid = threadIdx.x;
    const int wid = tid >> 5;
    const int l = tid & 31;

    const int bn = blockIdx.x;              // m tiles (128)
    const int bm = blockIdx.y + bm_off;     // np tiles (24 total)

    const int npwarp = (wid & 1) * 64;
    const int mwarp  = (wid >> 1) * 32;

    const uint32_t swz = (uint32_t)(l & 7) << 4;
    const uint32_t aRow = npwarp + (l & 15);
    const uint32_t aHalf = (uint32_t)(l >> 4) << 4;     // 0 or 16
    const uint32_t bRow = mwarp + (l & 7) + ((l & 16) >> 1);
    const uint32_t bHalf = (uint32_t)(l & 8) << 1;      // 0 or 16

    const char* aSrcBase = (const char*)g_wc + (size_t)bm * 128 * 128;
    const char* bSrcBase = (const char*)g_xc + (size_t)bn * 128 * 128;

    float cacc[4][4][4];
    #pragma unroll
    for (int i = 0; i < 4; i++)
        #pragma unroll
        for (int j = 0; j < 4; j++)
            #pragma unroll
            for (int r = 0; r < 4; r++) cacc[i][j][r] = 0.0f;

    auto issue_pos = [&](int kc, int slot) {
        const uint32_t sb = sbase + slot * STAGE_BYTES;
        const char* wh = aSrcBase + (size_t)kc * N_W * 128;
        const char* xh = bSrcBase + (size_t)kc * M_X * 128;
        #pragma unroll
        for (int r = 0; r < 4; r++) {
            int off = (tid + r * 256) * 16;
            cp_async16(sb + W_OFF + off, wh + off);
        }
        #pragma unroll
        for (int r = 0; r < 4; r++) {
            int off = (tid + r * 256) * 16;
            cp_async16(sb + X_OFF + off, xh + off);
        }
        cp_commit();
    };

    issue_pos(0, 0);
    issue_pos(1, 1);

    for (int j = 0; j < NPOS; j++) {
        const int slot = j % 3;
        cp_wait<1>();
        __syncthreads();
        if (j + 2 < NPOS) issue_pos(j + 2, (j + 2) % 3);

        const uint32_t sb = sbase + slot * STAGE_BYTES;

        #pragma unroll
        for (int ks = 0; ks < 4; ks++) {
            const uint32_t kb = ks * 32;
            const uint32_t aCol = (kb + aHalf) ^ swz;
            const uint32_t bCol = (kb + bHalf) ^ swz;

            uint32_t bh[2][4];
            #pragma unroll
            for (int g = 0; g < 2; g++) {
                ldsm_x4(bh[g][0], bh[g][1], bh[g][2], bh[g][3],
                        sb + X_OFF + (bRow + g * 16) * 128 + bCol);
            }
            #pragma unroll
            for (int t = 0; t < 4; t++) {
                uint32_t a[4];
                ldsm_x4(a[0], a[1], a[2], a[3],
                        sb + W_OFF + (aRow + t * 16) * 128 + aCol);
                #pragma unroll
                for (int jj = 0; jj < 4; jj++)
                    mma_fp16(cacc[t][jj], a, &bh[jj >> 1][(jj & 1) * 2]);
            }
        }
    }

    // ---------------- epilogue ----------------
    __syncthreads();
    float* stag = (float*)smem;    // [128 m][EPI_PITCH np]

    #pragma unroll
    for (int i = 0; i < 4; i++) {
        const int np0 = npwarp + i * 16 + (l >> 2);
        #pragma unroll
        for (int jj = 0; jj < 4; jj++) {
            const int m0 = mwarp + jj * 8 + (l & 3) * 2;
            stag[(size_t)m0 * EPI_PITCH + np0]           = cacc[i][jj][0];
            stag[(size_t)(m0 + 1) * EPI_PITCH + np0]     = cacc[i][jj][1];
            stag[(size_t)m0 * EPI_PITCH + np0 + 8]       = cacc[i][jj][2];
            stag[(size_t)(m0 + 1) * EPI_PITCH + np0 + 8] = cacc[i][jj][3];
        }
    }
    __syncthreads();

    const int gate = bm >> 3;
    const int d0 = (bm & 7) * 128;
    __half* plane = (gate == 0) ? g_u0 : ((gate == 1) ? g_g1 : g_g2);

    for (int idx = tid; idx < 128 * 64; idx += 256) {
        const int m = idx >> 6;
        const int np2 = (idx & 63) * 2;
        float v0 = stag[(size_t)m * EPI_PITCH + np2];
        float v1 = stag[(size_t)m * EPI_PITCH + np2 + 1];
        if (gate) {
            const float b0 = bias[(gate - 1) * D_SZ + d0 + np2];
            const float b1 = bias[(gate - 1) * D_SZ + d0 + np2 + 1];
            v0 = 1.0f / (1.0f + __expf(-(v0 + b0)));
            v1 = 1.0f / (1.0f + __expf(-(v1 + b1)));
        }
        __half2 hv = __floats2half2_rn(v0, v1);
        *reinterpret_cast<__half2*>(
            &plane[(size_t)(bn * 128 + m) * D_SZ + d0 + np2]) = hv;
    }
}

// ---------------------------------------------------------------------------
// Segmented scan (2 lanes per thread).  c_t = g1*c + u0*(1-g1)
// ---------------------------------------------------------------------------
__global__ __launch_bounds__(256)
void scan_seg_kernel() {
    const int gid = blockIdx.x * blockDim.x + threadIdx.x;  // NSEG * 8192
    const int lane2 = (gid & 8191) * 2;
    const int s = gid >> 13;
    size_t o = ((size_t)s * SEG_T * NLANE + lane2) >> 1;    // half2 index
    const __half2* __restrict__ u0 = (const __half2*)g_u0;
    const __half2* __restrict__ g1 = (const __half2*)g_g1;
    float A0 = 1.0f, B0 = 0.0f, A1 = 1.0f, B1 = 0.0f;
    #pragma unroll 8
    for (int t = 0; t < SEG_T; t++) {
        const float2 a = __half22float2(g1[o]);
        const float2 u = __half22float2(u0[o]);
        B0 = B0 * a.x + u.x * (1.0f - a.x);
        B1 = B1 * a.y + u.y * (1.0f - a.y);
        A0 *= a.x;
        A1 *= a.y;
        o += NLANE / 2;
    }
    *reinterpret_cast<float2*>(&g_segAx[s * NLANE + lane2]) = make_float2(A0, A1);
    *reinterpret_cast<float2*>(&g_segBx[s * NLANE + lane2]) = make_float2(B0, B1);
}

// Prefix across segments: prefetch ALL segment coefficients first (MLP=32),
// then run the short dependent chain. One lane per thread.
__global__ __launch_bounds__(256)
void scan_prefix_kernel(const float* __restrict__ c0) {
    const int lane = blockIdx.x * blockDim.x + threadIdx.x;  // 16384 threads
    float A[NSEG], Bv[NSEG];
    #pragma unroll
    for (int s = 0; s < NSEG; s++) A[s] = g_segAx[s * NLANE + lane];
    #pragma unroll
    for (int s = 0; s < NSEG; s++) Bv[s] = g_segBx[s * NLANE + lane];
    float c = c0[lane];
    #pragma unroll
    for (int s = 0; s < NSEG; s++) {
        g_cst[s * NLANE + lane] = c;
        c = A[s] * c + Bv[s];
    }
}

__global__ __launch_bounds__(256)
void scan_out_kernel(float* __restrict__ out) {
    const int gid = blockIdx.x * blockDim.x + threadIdx.x;  // NSEG * 8192
    const int lane2 = (gid & 8191) * 2;
    const int s = gid >> 13;
    const __half2* __restrict__ u0 = (const __half2*)g_u0;
    const __half2* __restrict__ g1 = (const __half2*)g_g1;
    const __half2* __restrict__ g2 = (const __half2*)g_g2;
    float2 c = *reinterpret_cast<const float2*>(&g_cst[s * NLANE + lane2]);
    size_t e = (size_t)s * SEG_T * NLANE + lane2;           // element index
    size_t o = e >> 1;                                      // half2 index

    // x read from the packed swizzled fp16 operand g_xc (d fixed, m += 16/t).
    const int m0 = (int)(e >> 10);          // initial row
    const int d  = lane2 & 1023;
    const char* xbase = (const char*)g_xc
        + ((size_t)(d >> 6) * M_X + m0) * 128
        + (((uint32_t)(d & 63) * 2) ^ (((uint32_t)m0 & 7u) << 4));

    #pragma unroll 4
    for (int t = 0; t < SEG_T; t++) {
        const float2 u = __half22float2(u0[o]);
        const float2 a = __half22float2(g1[o]);
        const float2 b = __half22float2(g2[o]);
        const float2 xv = __half22float2(
            *reinterpret_cast<const __half2*>(xbase + (size_t)t * 2048));
        c.x = (c.x - u.x) * a.x + u.x;
        c.y = (c.y - u.y) * a.y + u.y;
        float2 h;
        h.x = (tanh_fast(c.x) - xv.x) * b.x + xv.x;
        h.y = (tanh_fast(c.y) - xv.y) * b.y + xv.y;
        *reinterpret_cast<float2*>(&out[e]) = h;
        e += NLANE;
        o += NLANE / 2;
    }
    if (s == NSEG - 1)
        *reinterpret_cast<float2*>(&out[PLANE + lane2]) = c;   // c_last
}

// ---------------------------------------------------------------------------
// Launch: fork/join graph.
//   main: conv -> GEMM_A(gates 0,1) -> [evA] -> scan_seg -> prefix -> (wait evB)
//         -> scan_out
//   s2:   (wait evA) -> GEMM_B(gate 2) -> [evB]
// GEMM_B (tensor-bound) overlaps scan_seg+prefix (DRAM-bound).
// ---------------------------------------------------------------------------
extern "C" void kernel_launch(void* const* d_in, const int* in_sizes, int n_in,
                              void* d_out, int out_size) {
    const float* x      = (const float*)d_in[0];  // (L,B,D)
    const float* weight = (const float*)d_in[1];  // (D, 3D)
    const float* bias   = (const float*)d_in[2];  // (2D)
    const float* c0     = (const float*)d_in[3];  // (B,D)
    float* out = (float*)d_out;                   // h then c_last

    static int initialized = 0;
    static cudaStream_t s2;
    static cudaEvent_t evA, evB;
    if (!initialized) {
        cudaFuncSetAttribute(sru_gemm_mma, cudaFuncAttributeMaxDynamicSharedMemorySize,
                             SMEM_TOTAL);
        cudaStreamCreateWithFlags(&s2, cudaStreamNonBlocking);
        cudaEventCreateWithFlags(&evA, cudaEventDisableTiming);
        cudaEventCreateWithFlags(&evB, cudaEventDisableTiming);
        initialized = 1;
    }

    conv_kernel<<<CONVX_BLOCKS + CONVW_BLOCKS, 256>>>(x, weight);

    // GEMM A: gates 0 and 1 (bm 0..15)
    sru_gemm_mma<<<dim3(M_X / 128, 16), 256, SMEM_TOTAL>>>(bias, 0);
    cudaEventRecord(evA, 0);

    // GEMM B: gate 2 (bm 16..23) on side stream, overlapping scan_seg/prefix
    cudaStreamWaitEvent(s2, evA, 0);
    sru_gemm_mma<<<dim3(M_X / 128, 8), 256, SMEM_TOTAL, s2>>>(bias, 16);
    cudaEventRecord(evB, s2);

    // Main stream: scan_seg + prefix need only gates 0,1
    scan_seg_kernel<<<(NSEG * 8192) / 256, 256>>>();
    scan_prefix_kernel<<<NLANE / 256, 256>>>(c0);

    // Join: scan_out needs gate 2
    cudaStreamWaitEvent(0, evB, 0);
    scan_out_kernel<<<(NSEG * 8192) / 256, 256>>>(out);
}